// round 7
// baseline (speedup 1.0000x reference)
#include <cuda_runtime.h>
#include <cuda_fp16.h>
#include <cstdint>

#define B_ 4
#define T_ 2048
#define E_ 1024
#define H_ 128
#define M_ (B_*T_)   // 8192

// ---------------------------------------------------------------------------
// Scratch (__device__ globals; allocation-free rule)
// ---------------------------------------------------------------------------
__device__ __half g_wh[3*E_*H_];     // Wq|Wk|Wv in fp16
__device__ __half g_q[M_*H_];
__device__ __half g_k[M_*H_];
__device__ __half g_v[M_*H_];

// split-KV partials (only q-tiles with >1 chunk; max 4 chunks)
#define NPART (B_*16*4)
__device__ float g_po[NPART*128*128];   // 16 MB
__device__ float g_ml[NPART*128*2];

// chunking: nch(qt) = ceil((2qt+2)/8); 40 chunks per batch, heaviest first.
__constant__ int c_nch[16] = {1,1,1,1,2,2,2,2,3,3,3,3,4,4,4,4};
__constant__ int c_qt[40] = {
    15,15,15,15,14,14,11,11,11,10,7,7,3,          // 8-tile chunks (13)
    14,14,13,13,13,13,12,12,10,10,9,9,6,6,        // 7-tile chunks (14)
    12,12,9,8,8,8,5,5,2,                          // 6-tile chunks (9)
    4,4,                                          // 5
    1,                                            // 4
    0                                             // 2
};
__constant__ int c_ch[40] = {
    0,1,2,3,0,1,0,1,2,0,0,1,0,
    2,3,0,1,2,3,0,1,1,2,0,1,0,1,
    2,3,2,0,1,2,0,1,0,
    0,1,
    0,
    0
};

// ---------------------------------------------------------------------------
// PTX helpers
// ---------------------------------------------------------------------------
__device__ __forceinline__ unsigned smem_u32(const void* p) {
    return (unsigned)__cvta_generic_to_shared(p);
}
__device__ __forceinline__ void ldsm_x4(unsigned* r, unsigned a) {
    asm volatile("ldmatrix.sync.aligned.m8n8.x4.shared.b16 {%0,%1,%2,%3}, [%4];\n"
        : "=r"(r[0]), "=r"(r[1]), "=r"(r[2]), "=r"(r[3]) : "r"(a));
}
__device__ __forceinline__ void ldsm_x4_t(unsigned* r, unsigned a) {
    asm volatile("ldmatrix.sync.aligned.m8n8.x4.trans.shared.b16 {%0,%1,%2,%3}, [%4];\n"
        : "=r"(r[0]), "=r"(r[1]), "=r"(r[2]), "=r"(r[3]) : "r"(a));
}
__device__ __forceinline__ void mma_f16(float d[4], const unsigned a[4], const unsigned b[2]) {
    asm volatile(
        "mma.sync.aligned.m16n8k16.row.col.f32.f16.f16.f32 "
        "{%0,%1,%2,%3}, {%4,%5,%6,%7}, {%8,%9}, {%0,%1,%2,%3};\n"
        : "+f"(d[0]), "+f"(d[1]), "+f"(d[2]), "+f"(d[3])
        : "r"(a[0]), "r"(a[1]), "r"(a[2]), "r"(a[3]), "r"(b[0]), "r"(b[1]));
}
__device__ __forceinline__ void cp16(unsigned dst, const void* src) {
    asm volatile("cp.async.cg.shared.global [%0], [%1], 16;\n" :: "r"(dst), "l"(src));
}
__device__ __forceinline__ void cp_commit() { asm volatile("cp.async.commit_group;\n"); }
template<int N> __device__ __forceinline__ void cp_wait() {
    asm volatile("cp.async.wait_group %0;\n" :: "n"(N));
}
__device__ __forceinline__ unsigned packh2(float a, float b) {
    __half2 h = __floats2half2_rn(a, b);
    return *reinterpret_cast<unsigned*>(&h);
}

// ---------------------------------------------------------------------------
// Convert kernel: W only -> fp16 (x handled inside qkv)
// ---------------------------------------------------------------------------
__global__ __launch_bounds__(256) void convert_kernel(
    const float* __restrict__ Wq, const float* __restrict__ Wk,
    const float* __restrict__ Wv)
{
    const int nth = gridDim.x * blockDim.x;
    const int i0  = blockIdx.x * blockDim.x + threadIdx.x;
    const int WN = E_*H_/4;
    for (int i = i0; i < 3*WN; i += nth) {
        const float* W = (i < WN) ? Wq : (i < 2*WN ? Wk : Wv);
        int j = i - (i < WN ? 0 : (i < 2*WN ? WN : 2*WN));
        float4 f = ((const float4*)W)[j];
        ((__half2*)g_wh)[i*2]   = __floats2half2_rn(f.x, f.y);
        ((__half2*)g_wh)[i*2+1] = __floats2half2_rn(f.z, f.w);
    }
}

// ---------------------------------------------------------------------------
// QKV projection: out = x @ W + b. x read as fp32 + in-kernel cvt (reg
// double-buffered); W fp16 via cp.async. BM=64, BN=128, BK=64, 8 warps.
// ---------------------------------------------------------------------------
#define QKV_AP 72
#define QKV_BP 136
#define QKV_ABUF (64*QKV_AP)
#define QKV_BBUF (64*QKV_BP)
#define QKV_SMEM_BYTES ((2*QKV_ABUF + 2*QKV_BBUF)*2)

__global__ __launch_bounds__(256) void qkv_kernel(
    const float* __restrict__ x,
    const float* __restrict__ bq, const float* __restrict__ bk,
    const float* __restrict__ bv)
{
    extern __shared__ __half smh[];
    __half* As = smh;                    // 2 x 64x72
    __half* Bs = smh + 2*QKV_ABUF;       // 2 x 64x136

    const int z = blockIdx.y;
    const float* bias = (z == 0) ? bq : (z == 1 ? bk : bv);
    __half* out = (z == 0) ? g_q : (z == 1 ? g_k : g_v);
    const __half* wh = g_wh + (size_t)z*E_*H_;

    const int m0   = blockIdx.x * 64;
    const int tid  = threadIdx.x;
    const int w    = tid >> 5;
    const int lane = tid & 31;
    const int g    = lane >> 2;
    const int tg   = lane & 3;
    const int lr   = lane & 7;
    const int seg  = lane >> 3;
    const int rb0  = (w & 3) * 16;
    const int cb   = (w >> 2) * 64;

    float acc[8][4];
    #pragma unroll
    for (int nt = 0; nt < 8; nt++)
        #pragma unroll
        for (int q = 0; q < 4; q++) acc[nt][q] = 0.f;

    float4 a_reg[4];
    auto ldgA = [&](int it) {
        const int k0 = it * 64;
        #pragma unroll
        for (int t = 0; t < 4; t++) {
            int i = tid + t*256;
            int r = i >> 4, c4 = i & 15;
            a_reg[t] = *(const float4*)&x[(size_t)(m0 + r)*E_ + k0 + c4*4];
        }
    };
    auto stsA = [&](int it) {
        #pragma unroll
        for (int t = 0; t < 4; t++) {
            int i = tid + t*256;
            int r = i >> 4, c4 = i & 15;
            __half2 h0 = __floats2half2_rn(a_reg[t].x, a_reg[t].y);
            __half2 h1 = __floats2half2_rn(a_reg[t].z, a_reg[t].w);
            __half2* p = (__half2*)&As[(it&1)*QKV_ABUF + r*QKV_AP + c4*4];
            p[0] = h0; p[1] = h1;
        }
    };
    auto cpB = [&](int it) {
        const int k0 = it * 64;
        #pragma unroll
        for (int t = 0; t < 4; t++) {
            int i = tid + t*256;
            int r = i >> 4, c = i & 15;
            cp16(smem_u32(&Bs[(it&1)*QKV_BBUF + r*QKV_BP + c*8]),
                 &wh[(size_t)(k0 + r)*H_ + c*8]);
        }
    };

    ldgA(0);
    cpB(0); cp_commit();

    for (int it = 0; it < 16; it++) {
        stsA(it);
        if (it + 1 < 16) {
            ldgA(it+1);
            cpB(it+1); cp_commit();
            cp_wait<1>();
        } else {
            cp_wait<0>();
        }
        __syncthreads();

        const __half* Ab = As + (it&1)*QKV_ABUF;
        const __half* Bb = Bs + (it&1)*QKV_BBUF;
        const unsigned abase = smem_u32(Ab) +
            ((rb0 + lr + (seg&1)*8)*QKV_AP + (seg>>1)*8)*2;
        const unsigned bbase = smem_u32(Bb) +
            (((seg&1)*8 + lr)*QKV_BP + cb + (seg>>1)*8)*2;

        #pragma unroll
        for (int ks = 0; ks < 4; ks++) {
            unsigned a[4];
            ldsm_x4(a, abase + ks*32);
            #pragma unroll
            for (int ntp = 0; ntp < 4; ntp++) {
                unsigned b[4];
                ldsm_x4_t(b, bbase + (ks*16*QKV_BP + ntp*16)*2);
                mma_f16(acc[ntp*2],   a, b);
                mma_f16(acc[ntp*2+1], a, b+2);
            }
        }
        __syncthreads();
    }

    #pragma unroll
    for (int r2 = 0; r2 < 2; r2++) {
        int row = m0 + rb0 + g + r2*8;
        #pragma unroll
        for (int nt = 0; nt < 8; nt++) {
            int col = cb + nt*8 + 2*tg;
            __half2 o = __floats2half2_rn(acc[nt][r2*2+0] + bias[col],
                                          acc[nt][r2*2+1] + bias[col+1]);
            *(__half2*)&out[(size_t)row*H_ + col] = o;
        }
    }
}

// ---------------------------------------------------------------------------
// Split-KV flash attention, fp16 mma, register P, double-buffered K/V.
// Br=128, Bc=64. Chunks of <=8 KV tiles, heaviest CTAs first.
// ---------------------------------------------------------------------------
#define PH 136
#define QS_H   (128*PH)
#define KV_H   (64*PH)
#define ATT_SMEM_BYTES ((QS_H + 4*KV_H)*2)
#define SCALE 0.08838834764831845f  // 1/sqrt(128)

__global__ __launch_bounds__(256) void attn_kernel(float* __restrict__ outp)
{
    extern __shared__ __half smh[];
    __half* Qs = smh;                 // 128 x 136
    __half* Ks = smh + QS_H;          // 2 x (64 x 136)
    __half* Vs = smh + QS_H + 2*KV_H; // 2 x (64 x 136)

    const int qt = c_qt[blockIdx.x];
    const int ch = c_ch[blockIdx.x];
    const int bb = blockIdx.y;
    const int m0 = qt * 128;

    // even-split chunk bounds
    const int nTiles = 2*qt + 2;
    const int nch = c_nch[qt];
    const int bsz = nTiles / nch, rem = nTiles % nch;
    const int t0 = ch*bsz + (ch < rem ? ch : rem);
    const int t1 = t0 + bsz + (ch < rem ? 1 : 0);

    const __half* qg = g_q + (size_t)bb*T_*H_;
    const __half* kg = g_k + (size_t)bb*T_*H_;
    const __half* vg = g_v + (size_t)bb*T_*H_;

    const int tid  = threadIdx.x;
    const int w    = tid >> 5;
    const int lane = tid & 31;
    const int g    = lane >> 2;
    const int tg   = lane & 3;
    const int lr   = lane & 7;
    const int seg  = lane >> 3;
    const int rb   = w * 16;

    auto load_kv = [&](int jt) {
        const int j0 = jt * 64;
        __half* Kd = Ks + (jt&1)*KV_H;
        __half* Vd = Vs + (jt&1)*KV_H;
        #pragma unroll
        for (int t = 0; t < 4; t++) {
            int i = tid + t*256;
            int r = i >> 4, c = i & 15;
            cp16(smem_u32(&Kd[r*PH + c*8]), &kg[(size_t)(j0 + r)*H_ + c*8]);
            cp16(smem_u32(&Vd[r*PH + c*8]), &vg[(size_t)(j0 + r)*H_ + c*8]);
        }
    };

    #pragma unroll
    for (int t = 0; t < 8; t++) {
        int i = tid + t*256;
        int r = i >> 4, c = i & 15;
        cp16(smem_u32(&Qs[r*PH + c*8]), &qg[(size_t)(m0 + r)*H_ + c*8]);
    }
    load_kv(t0);
    cp_commit();

    float o[16][4];
    #pragma unroll
    for (int nt = 0; nt < 16; nt++)
        #pragma unroll
        for (int q = 0; q < 4; q++) o[nt][q] = 0.f;
    float m_i[2] = {-1e30f, -1e30f};
    float l_i[2] = {0.f, 0.f};

    const unsigned qbase = smem_u32(Qs) + ((rb + lr + (seg&1)*8)*PH + (seg>>1)*8)*2;

    for (int jt = t0; jt < t1; jt++) {
        if (jt + 1 < t1) { load_kv(jt+1); cp_commit(); cp_wait<1>(); }
        else             { cp_wait<0>(); }
        __syncthreads();

        const __half* Kb = Ks + (jt&1)*KV_H;
        const __half* Vb = Vs + (jt&1)*KV_H;
        const unsigned kbase = smem_u32(Kb) + (((seg>>1)*8 + lr)*PH + (seg&1)*8)*2;
        const unsigned vbase = smem_u32(Vb) + (((seg&1)*8 + lr)*PH + (seg>>1)*8)*2;

        // ---- S = Q @ K^T ----
        float s[8][4];
        #pragma unroll
        for (int nt = 0; nt < 8; nt++)
            #pragma unroll
            for (int q = 0; q < 4; q++) s[nt][q] = 0.f;

        #pragma unroll
        for (int ks = 0; ks < 8; ks++) {
            unsigned a[4];
            ldsm_x4(a, qbase + ks*32);
            #pragma unroll
            for (int ntp = 0; ntp < 4; ntp++) {
                unsigned b[4];
                ldsm_x4(b, kbase + (ntp*16*PH)*2 + ks*32);
                mma_f16(s[ntp*2],   a, b);
                mma_f16(s[ntp*2+1], a, b+2);
            }
        }

        // ---- online softmax -> P packed in registers ----
        const int j0 = jt * 64;
        const bool need_mask = (j0 + 64 > m0);
        unsigned pp[8][2];
        #pragma unroll
        for (int r2 = 0; r2 < 2; r2++) {
            const int grow = m0 + rb + g + r2*8;
            float vv[8][2];
            float mloc = -1e30f;
            #pragma unroll
            for (int nt = 0; nt < 8; nt++) {
                float v0 = s[nt][r2*2+0] * SCALE;
                float v1 = s[nt][r2*2+1] * SCALE;
                if (need_mask) {
                    int c0 = j0 + nt*8 + 2*tg;
                    if (c0     > grow) v0 = -1e30f;
                    if (c0 + 1 > grow) v1 = -1e30f;
                }
                vv[nt][0] = v0; vv[nt][1] = v1;
                mloc = fmaxf(mloc, fmaxf(v0, v1));
            }
            mloc = fmaxf(mloc, __shfl_xor_sync(0xffffffffu, mloc, 1));
            mloc = fmaxf(mloc, __shfl_xor_sync(0xffffffffu, mloc, 2));
            float m_new = fmaxf(m_i[r2], mloc);
            float alpha = __expf(m_i[r2] - m_new);
            float rs = 0.f;
            #pragma unroll
            for (int nt = 0; nt < 8; nt++) {
                float p0 = __expf(vv[nt][0] - m_new);
                float p1 = __expf(vv[nt][1] - m_new);
                rs += p0 + p1;
                pp[nt][r2] = packh2(p0, p1);
            }
            rs += __shfl_xor_sync(0xffffffffu, rs, 1);
            rs += __shfl_xor_sync(0xffffffffu, rs, 2);
            l_i[r2] = l_i[r2]*alpha + rs;
            m_i[r2] = m_new;
            #pragma unroll
            for (int nt = 0; nt < 16; nt++) {
                o[nt][r2*2+0] *= alpha;
                o[nt][r2*2+1] *= alpha;
            }
        }

        // ---- O += P @ V ----
        #pragma unroll
        for (int ks = 0; ks < 4; ks++) {
            unsigned a[4] = { pp[2*ks][0], pp[2*ks][1], pp[2*ks+1][0], pp[2*ks+1][1] };
            #pragma unroll
            for (int ntp = 0; ntp < 8; ntp++) {
                unsigned b[4];
                ldsm_x4_t(b, vbase + (ks*16*PH + ntp*16)*2);
                mma_f16(o[ntp*2],   a, b);
                mma_f16(o[ntp*2+1], a, b+2);
            }
        }
        __syncthreads();
    }

    if (nch == 1) {
        float* og = outp + ((size_t)bb*T_ + m0)*H_;
        #pragma unroll
        for (int r2 = 0; r2 < 2; r2++) {
            float inv = 1.0f / l_i[r2];
            int row = rb + g + r2*8;
            #pragma unroll
            for (int nt = 0; nt < 16; nt++) {
                int col = nt*8 + 2*tg;
                float2 oo;
                oo.x = o[nt][r2*2+0] * inv;
                oo.y = o[nt][r2*2+1] * inv;
                *(float2*)&og[(size_t)row*H_ + col] = oo;
            }
        }
    } else {
        const int part = (bb*16 + qt)*4 + ch;
        float* po = g_po + (size_t)part*16384;
        #pragma unroll
        for (int r2 = 0; r2 < 2; r2++) {
            int row = rb + g + r2*8;
            #pragma unroll
            for (int nt = 0; nt < 16; nt++) {
                int col = nt*8 + 2*tg;
                float2 oo;
                oo.x = o[nt][r2*2+0];
                oo.y = o[nt][r2*2+1];
                *(float2*)&po[row*128 + col] = oo;
            }
            if (tg == 0) {
                g_ml[part*256 + row*2    ] = m_i[r2];
                g_ml[part*256 + row*2 + 1] = l_i[r2];
            }
        }
    }
}

// ---------------------------------------------------------------------------
// Merge: q-tiles 4..15. grid (12, B, 8 row-splits of 16 rows).
// ---------------------------------------------------------------------------
__global__ __launch_bounds__(256) void merge_kernel(float* __restrict__ out)
{
    const int qt = 4 + blockIdx.x;
    const int bb = blockIdx.y;
    const int r0 = blockIdx.z * 16;
    const int nch = c_nch[qt];
    const int base = (bb*16 + qt)*4;

    __shared__ float ws[4][16];
    __shared__ float invd[16];

    const int tid = threadIdx.x;
    if (tid < 16) {
        int row = r0 + tid;
        float mv[4];
        float m_max = -1e30f;
        for (int c = 0; c < nch; c++) {
            mv[c] = g_ml[(base+c)*256 + row*2];
            m_max = fmaxf(m_max, mv[c]);
        }
        float denom = 0.f;
        for (int c = 0; c < nch; c++) {
            float wv = __expf(mv[c] - m_max);
            ws[c][tid] = wv;
            denom += wv * g_ml[(base+c)*256 + row*2 + 1];
        }
        invd[tid] = 1.0f / denom;
    }
    __syncthreads();

    #pragma unroll
    for (int it = 0; it < 2; it++) {
        int idx = tid + it*256;            // 0..511: 16 rows x 32 float4
        int row = idx >> 5, c4 = idx & 31;
        float4 acc = make_float4(0.f, 0.f, 0.f, 0.f);
        for (int c = 0; c < nch; c++) {
            float4 p = *(const float4*)&g_po[(size_t)(base+c)*16384 + (r0+row)*128 + c4*4];
            float wv = ws[c][row];
            acc.x += wv*p.x; acc.y += wv*p.y; acc.z += wv*p.z; acc.w += wv*p.w;
        }
        float iv = invd[row];
        acc.x *= iv; acc.y *= iv; acc.z *= iv; acc.w *= iv;
        *(float4*)&out[((size_t)bb*T_ + qt*128 + r0 + row)*H_ + c4*4] = acc;
    }
}

// ---------------------------------------------------------------------------
extern "C" void kernel_launch(void* const* d_in, const int* in_sizes, int n_in,
                              void* d_out, int out_size)
{
    const float* x  = (const float*)d_in[0];
    const float* Wq = (const float*)d_in[1];
    const float* bq = (const float*)d_in[2];
    const float* Wk = (const float*)d_in[3];
    const float* bk = (const float*)d_in[4];
    const float* Wv = (const float*)d_in[5];
    const float* bv = (const float*)d_in[6];
    float* out = (float*)d_out;

    convert_kernel<<<96, 256>>>(Wq, Wk, Wv);

    cudaFuncSetAttribute(qkv_kernel,
                         cudaFuncAttributeMaxDynamicSharedMemorySize, QKV_SMEM_BYTES);
    qkv_kernel<<<dim3(M_/64, 3), 256, QKV_SMEM_BYTES>>>(x, bq, bk, bv);

    cudaFuncSetAttribute(attn_kernel,
                         cudaFuncAttributeMaxDynamicSharedMemorySize, ATT_SMEM_BYTES);
    attn_kernel<<<dim3(40, B_), 256, ATT_SMEM_BYTES>>>(out);

    merge_kernel<<<dim3(12, B_, 8), 256>>>(out);
}

// round 8
// speedup vs baseline: 1.0270x; 1.0270x over previous
#include <cuda_runtime.h>
#include <cuda_fp16.h>
#include <cstdint>

#define B_ 4
#define T_ 2048
#define E_ 1024
#define H_ 128
#define M_ (B_*T_)   // 8192

// ---------------------------------------------------------------------------
// Scratch (__device__ globals; allocation-free rule)
// ---------------------------------------------------------------------------
__device__ __half g_wh[3*E_*H_];     // Wq|Wk|Wv in fp16
__device__ __half g_q[M_*H_];
__device__ __half g_k[M_*H_];
__device__ __half g_v[M_*H_];

// split-KV partials (only q-tiles with >1 chunk; max 4 chunks)
#define NPART (B_*16*4)
__device__ float g_po[NPART*128*128];   // 16 MB
__device__ float g_ml[NPART*128*2];

// R6 chunking: 34 chunks/batch -> 136 CTAs (single wave on 148 SMs)
__constant__ int c_qt[34] = {0,1,2,3,4, 5,5,6,6,7,7,8,8,9,9,
                             10,10,10,11,11,11,12,12,12,13,13,13,14,14,14,
                             15,15,15,15};
__constant__ int c_ch[34] = {0,0,0,0,0, 0,1,0,1,0,1,0,1,0,1,
                             0,1,2,0,1,2,0,1,2,0,1,2,0,1,2,
                             0,1,2,3};
__constant__ int c_nch[16] = {1,1,1,1,1,2,2,2,2,2,3,3,3,3,3,4};

// ---------------------------------------------------------------------------
// PTX helpers
// ---------------------------------------------------------------------------
__device__ __forceinline__ unsigned smem_u32(const void* p) {
    return (unsigned)__cvta_generic_to_shared(p);
}
__device__ __forceinline__ void ldsm_x4(unsigned* r, unsigned a) {
    asm volatile("ldmatrix.sync.aligned.m8n8.x4.shared.b16 {%0,%1,%2,%3}, [%4];\n"
        : "=r"(r[0]), "=r"(r[1]), "=r"(r[2]), "=r"(r[3]) : "r"(a));
}
__device__ __forceinline__ void ldsm_x4_t(unsigned* r, unsigned a) {
    asm volatile("ldmatrix.sync.aligned.m8n8.x4.trans.shared.b16 {%0,%1,%2,%3}, [%4];\n"
        : "=r"(r[0]), "=r"(r[1]), "=r"(r[2]), "=r"(r[3]) : "r"(a));
}
__device__ __forceinline__ void mma_f16(float d[4], const unsigned a[4], const unsigned b[2]) {
    asm volatile(
        "mma.sync.aligned.m16n8k16.row.col.f32.f16.f16.f32 "
        "{%0,%1,%2,%3}, {%4,%5,%6,%7}, {%8,%9}, {%0,%1,%2,%3};\n"
        : "+f"(d[0]), "+f"(d[1]), "+f"(d[2]), "+f"(d[3])
        : "r"(a[0]), "r"(a[1]), "r"(a[2]), "r"(a[3]), "r"(b[0]), "r"(b[1]));
}
__device__ __forceinline__ void cp16(unsigned dst, const void* src) {
    asm volatile("cp.async.cg.shared.global [%0], [%1], 16;\n" :: "r"(dst), "l"(src));
}
__device__ __forceinline__ void cp_commit() { asm volatile("cp.async.commit_group;\n"); }
template<int N> __device__ __forceinline__ void cp_wait() {
    asm volatile("cp.async.wait_group %0;\n" :: "n"(N));
}
__device__ __forceinline__ unsigned packh2(float a, float b) {
    __half2 h = __floats2half2_rn(a, b);
    return *reinterpret_cast<unsigned*>(&h);
}

// ---------------------------------------------------------------------------
// Convert kernel: W only -> fp16 (x handled inside qkv)
// ---------------------------------------------------------------------------
__global__ __launch_bounds__(256) void convert_kernel(
    const float* __restrict__ Wq, const float* __restrict__ Wk,
    const float* __restrict__ Wv)
{
    const int nth = gridDim.x * blockDim.x;
    const int i0  = blockIdx.x * blockDim.x + threadIdx.x;
    const int WN = E_*H_/4;
    for (int i = i0; i < 3*WN; i += nth) {
        const float* W = (i < WN) ? Wq : (i < 2*WN ? Wk : Wv);
        int j = i - (i < WN ? 0 : (i < 2*WN ? WN : 2*WN));
        float4 f = ((const float4*)W)[j];
        ((__half2*)g_wh)[i*2]   = __floats2half2_rn(f.x, f.y);
        ((__half2*)g_wh)[i*2+1] = __floats2half2_rn(f.z, f.w);
    }
}

// ---------------------------------------------------------------------------
// QKV projection: out = x @ W + b. x read as fp32 + in-kernel cvt (reg
// double-buffered); W fp16 via cp.async. BM=64, BN=128, BK=64, 8 warps.
// ---------------------------------------------------------------------------
#define QKV_AP 72
#define QKV_BP 136
#define QKV_ABUF (64*QKV_AP)
#define QKV_BBUF (64*QKV_BP)
#define QKV_SMEM_BYTES ((2*QKV_ABUF + 2*QKV_BBUF)*2)

__global__ __launch_bounds__(256) void qkv_kernel(
    const float* __restrict__ x,
    const float* __restrict__ bq, const float* __restrict__ bk,
    const float* __restrict__ bv)
{
    extern __shared__ __half smh[];
    __half* As = smh;                    // 2 x 64x72
    __half* Bs = smh + 2*QKV_ABUF;       // 2 x 64x136

    const int z = blockIdx.y;
    const float* bias = (z == 0) ? bq : (z == 1 ? bk : bv);
    __half* out = (z == 0) ? g_q : (z == 1 ? g_k : g_v);
    const __half* wh = g_wh + (size_t)z*E_*H_;

    const int m0   = blockIdx.x * 64;
    const int tid  = threadIdx.x;
    const int w    = tid >> 5;
    const int lane = tid & 31;
    const int g    = lane >> 2;
    const int tg   = lane & 3;
    const int lr   = lane & 7;
    const int seg  = lane >> 3;
    const int rb0  = (w & 3) * 16;
    const int cb   = (w >> 2) * 64;

    float acc[8][4];
    #pragma unroll
    for (int nt = 0; nt < 8; nt++)
        #pragma unroll
        for (int q = 0; q < 4; q++) acc[nt][q] = 0.f;

    float4 a_reg[4];
    auto ldgA = [&](int it) {
        const int k0 = it * 64;
        #pragma unroll
        for (int t = 0; t < 4; t++) {
            int i = tid + t*256;
            int r = i >> 4, c4 = i & 15;
            a_reg[t] = *(const float4*)&x[(size_t)(m0 + r)*E_ + k0 + c4*4];
        }
    };
    auto stsA = [&](int it) {
        #pragma unroll
        for (int t = 0; t < 4; t++) {
            int i = tid + t*256;
            int r = i >> 4, c4 = i & 15;
            __half2 h0 = __floats2half2_rn(a_reg[t].x, a_reg[t].y);
            __half2 h1 = __floats2half2_rn(a_reg[t].z, a_reg[t].w);
            __half2* p = (__half2*)&As[(it&1)*QKV_ABUF + r*QKV_AP + c4*4];
            p[0] = h0; p[1] = h1;
        }
    };
    auto cpB = [&](int it) {
        const int k0 = it * 64;
        #pragma unroll
        for (int t = 0; t < 4; t++) {
            int i = tid + t*256;
            int r = i >> 4, c = i & 15;
            cp16(smem_u32(&Bs[(it&1)*QKV_BBUF + r*QKV_BP + c*8]),
                 &wh[(size_t)(k0 + r)*H_ + c*8]);
        }
    };

    ldgA(0);
    cpB(0); cp_commit();

    for (int it = 0; it < 16; it++) {
        stsA(it);
        if (it + 1 < 16) {
            ldgA(it+1);
            cpB(it+1); cp_commit();
            cp_wait<1>();
        } else {
            cp_wait<0>();
        }
        __syncthreads();

        const __half* Ab = As + (it&1)*QKV_ABUF;
        const __half* Bb = Bs + (it&1)*QKV_BBUF;
        const unsigned abase = smem_u32(Ab) +
            ((rb0 + lr + (seg&1)*8)*QKV_AP + (seg>>1)*8)*2;
        const unsigned bbase = smem_u32(Bb) +
            (((seg&1)*8 + lr)*QKV_BP + cb + (seg>>1)*8)*2;

        #pragma unroll
        for (int ks = 0; ks < 4; ks++) {
            unsigned a[4];
            ldsm_x4(a, abase + ks*32);
            #pragma unroll
            for (int ntp = 0; ntp < 4; ntp++) {
                unsigned b[4];
                ldsm_x4_t(b, bbase + (ks*16*QKV_BP + ntp*16)*2);
                mma_f16(acc[ntp*2],   a, b);
                mma_f16(acc[ntp*2+1], a, b+2);
            }
        }
        __syncthreads();
    }

    #pragma unroll
    for (int r2 = 0; r2 < 2; r2++) {
        int row = m0 + rb0 + g + r2*8;
        #pragma unroll
        for (int nt = 0; nt < 8; nt++) {
            int col = cb + nt*8 + 2*tg;
            __half2 o = __floats2half2_rn(acc[nt][r2*2+0] + bias[col],
                                          acc[nt][r2*2+1] + bias[col+1]);
            *(__half2*)&out[(size_t)row*H_ + col] = o;
        }
    }
}

// ---------------------------------------------------------------------------
// Split-KV flash attention, fp16 mma, register P, double-buffered K/V,
// Q fragments hoisted into registers. Br=128, Bc=64.
// ---------------------------------------------------------------------------
#define PH 136
#define QS_H   (128*PH)
#define KV_H   (64*PH)
#define ATT_SMEM_BYTES ((QS_H + 4*KV_H)*2)
#define SCALE 0.08838834764831845f  // 1/sqrt(128)

__global__ __launch_bounds__(256) void attn_kernel(float* __restrict__ outp)
{
    extern __shared__ __half smh[];
    __half* Qs = smh;                 // 128 x 136
    __half* Ks = smh + QS_H;          // 2 x (64 x 136)
    __half* Vs = smh + QS_H + 2*KV_H; // 2 x (64 x 136)

    const int qt = c_qt[blockIdx.x];
    const int ch = c_ch[blockIdx.x];
    const int bb = blockIdx.y;
    const int m0 = qt * 128;

    // even-split chunk bounds
    const int nTiles = 2*qt + 2;
    const int nch = c_nch[qt];
    const int bsz = nTiles / nch, rem = nTiles % nch;
    const int t0 = ch*bsz + (ch < rem ? ch : rem);
    const int t1 = t0 + bsz + (ch < rem ? 1 : 0);

    const __half* qg = g_q + (size_t)bb*T_*H_;
    const __half* kg = g_k + (size_t)bb*T_*H_;
    const __half* vg = g_v + (size_t)bb*T_*H_;

    const int tid  = threadIdx.x;
    const int w    = tid >> 5;
    const int lane = tid & 31;
    const int g    = lane >> 2;
    const int tg   = lane & 3;
    const int lr   = lane & 7;
    const int seg  = lane >> 3;
    const int rb   = w * 16;

    auto load_kv = [&](int jt) {
        const int j0 = jt * 64;
        __half* Kd = Ks + (jt&1)*KV_H;
        __half* Vd = Vs + (jt&1)*KV_H;
        #pragma unroll
        for (int t = 0; t < 4; t++) {
            int i = tid + t*256;
            int r = i >> 4, c = i & 15;
            cp16(smem_u32(&Kd[r*PH + c*8]), &kg[(size_t)(j0 + r)*H_ + c*8]);
            cp16(smem_u32(&Vd[r*PH + c*8]), &vg[(size_t)(j0 + r)*H_ + c*8]);
        }
    };

    #pragma unroll
    for (int t = 0; t < 8; t++) {
        int i = tid + t*256;
        int r = i >> 4, c = i & 15;
        cp16(smem_u32(&Qs[r*PH + c*8]), &qg[(size_t)(m0 + r)*H_ + c*8]);
    }
    load_kv(t0);
    cp_commit();

    float o[16][4];
    #pragma unroll
    for (int nt = 0; nt < 16; nt++)
        #pragma unroll
        for (int q = 0; q < 4; q++) o[nt][q] = 0.f;
    float m_i[2] = {-1e30f, -1e30f};
    float l_i[2] = {0.f, 0.f};

    const unsigned qbase = smem_u32(Qs) + ((rb + lr + (seg&1)*8)*PH + (seg>>1)*8)*2;
    unsigned qf[8][4];           // Q fragments, loaded once after first wait
    bool qf_loaded = false;

    for (int jt = t0; jt < t1; jt++) {
        if (jt + 1 < t1) { load_kv(jt+1); cp_commit(); cp_wait<1>(); }
        else             { cp_wait<0>(); }
        __syncthreads();

        if (!qf_loaded) {
            #pragma unroll
            for (int ks = 0; ks < 8; ks++) ldsm_x4(qf[ks], qbase + ks*32);
            qf_loaded = true;
        }

        const __half* Kb = Ks + (jt&1)*KV_H;
        const __half* Vb = Vs + (jt&1)*KV_H;
        const unsigned kbase = smem_u32(Kb) + (((seg>>1)*8 + lr)*PH + (seg&1)*8)*2;
        const unsigned vbase = smem_u32(Vb) + (((seg&1)*8 + lr)*PH + (seg>>1)*8)*2;

        // ---- S = Q @ K^T ----
        float s[8][4];
        #pragma unroll
        for (int nt = 0; nt < 8; nt++)
            #pragma unroll
            for (int q = 0; q < 4; q++) s[nt][q] = 0.f;

        #pragma unroll
        for (int ks = 0; ks < 8; ks++) {
            #pragma unroll
            for (int ntp = 0; ntp < 4; ntp++) {
                unsigned b[4];
                ldsm_x4(b, kbase + (ntp*16*PH)*2 + ks*32);
                mma_f16(s[ntp*2],   qf[ks], b);
                mma_f16(s[ntp*2+1], qf[ks], b+2);
            }
        }

        // ---- online softmax -> P packed in registers ----
        const int j0 = jt * 64;
        const bool need_mask = (j0 + 64 > m0);
        unsigned pp[8][2];
        #pragma unroll
        for (int r2 = 0; r2 < 2; r2++) {
            const int grow = m0 + rb + g + r2*8;
            float vv[8][2];
            float mloc = -1e30f;
            #pragma unroll
            for (int nt = 0; nt < 8; nt++) {
                float v0 = s[nt][r2*2+0] * SCALE;
                float v1 = s[nt][r2*2+1] * SCALE;
                if (need_mask) {
                    int c0 = j0 + nt*8 + 2*tg;
                    if (c0     > grow) v0 = -1e30f;
                    if (c0 + 1 > grow) v1 = -1e30f;
                }
                vv[nt][0] = v0; vv[nt][1] = v1;
                mloc = fmaxf(mloc, fmaxf(v0, v1));
            }
            mloc = fmaxf(mloc, __shfl_xor_sync(0xffffffffu, mloc, 1));
            mloc = fmaxf(mloc, __shfl_xor_sync(0xffffffffu, mloc, 2));
            float m_new = fmaxf(m_i[r2], mloc);
            float alpha = __expf(m_i[r2] - m_new);
            float rs = 0.f;
            #pragma unroll
            for (int nt = 0; nt < 8; nt++) {
                float p0 = __expf(vv[nt][0] - m_new);
                float p1 = __expf(vv[nt][1] - m_new);
                rs += p0 + p1;
                pp[nt][r2] = packh2(p0, p1);
            }
            rs += __shfl_xor_sync(0xffffffffu, rs, 1);
            rs += __shfl_xor_sync(0xffffffffu, rs, 2);
            l_i[r2] = l_i[r2]*alpha + rs;
            m_i[r2] = m_new;
            #pragma unroll
            for (int nt = 0; nt < 16; nt++) {
                o[nt][r2*2+0] *= alpha;
                o[nt][r2*2+1] *= alpha;
            }
        }

        // ---- O += P @ V ----
        #pragma unroll
        for (int ks = 0; ks < 4; ks++) {
            unsigned a[4] = { pp[2*ks][0], pp[2*ks][1], pp[2*ks+1][0], pp[2*ks+1][1] };
            #pragma unroll
            for (int ntp = 0; ntp < 8; ntp++) {
                unsigned b[4];
                ldsm_x4_t(b, vbase + (ks*16*PH + ntp*16)*2);
                mma_f16(o[ntp*2],   a, b);
                mma_f16(o[ntp*2+1], a, b+2);
            }
        }
        __syncthreads();
    }

    if (nch == 1) {
        float* og = outp + ((size_t)bb*T_ + m0)*H_;
        #pragma unroll
        for (int r2 = 0; r2 < 2; r2++) {
            float inv = 1.0f / l_i[r2];
            int row = rb + g + r2*8;
            #pragma unroll
            for (int nt = 0; nt < 16; nt++) {
                int col = nt*8 + 2*tg;
                float2 oo;
                oo.x = o[nt][r2*2+0] * inv;
                oo.y = o[nt][r2*2+1] * inv;
                *(float2*)&og[(size_t)row*H_ + col] = oo;
            }
        }
    } else {
        const int part = (bb*16 + qt)*4 + ch;
        float* po = g_po + (size_t)part*16384;
        #pragma unroll
        for (int r2 = 0; r2 < 2; r2++) {
            int row = rb + g + r2*8;
            #pragma unroll
            for (int nt = 0; nt < 16; nt++) {
                int col = nt*8 + 2*tg;
                float2 oo;
                oo.x = o[nt][r2*2+0];
                oo.y = o[nt][r2*2+1];
                *(float2*)&po[row*128 + col] = oo;
            }
            if (tg == 0) {
                g_ml[part*256 + row*2    ] = m_i[r2];
                g_ml[part*256 + row*2 + 1] = l_i[r2];
            }
        }
    }
}

// ---------------------------------------------------------------------------
// Merge: q-tiles 5..15. grid (11, B, 8 row-splits of 16 rows).
// ---------------------------------------------------------------------------
__global__ __launch_bounds__(256) void merge_kernel(float* __restrict__ out)
{
    const int qt = 5 + blockIdx.x;
    const int bb = blockIdx.y;
    const int r0 = blockIdx.z * 16;
    const int nch = c_nch[qt];
    const int base = (bb*16 + qt)*4;

    __shared__ float ws[4][16];
    __shared__ float invd[16];

    const int tid = threadIdx.x;
    if (tid < 16) {
        int row = r0 + tid;
        float mv[4];
        float m_max = -1e30f;
        for (int c = 0; c < nch; c++) {
            mv[c] = g_ml[(base+c)*256 + row*2];
            m_max = fmaxf(m_max, mv[c]);
        }
        float denom = 0.f;
        for (int c = 0; c < nch; c++) {
            float wv = __expf(mv[c] - m_max);
            ws[c][tid] = wv;
            denom += wv * g_ml[(base+c)*256 + row*2 + 1];
        }
        invd[tid] = 1.0f / denom;
    }
    __syncthreads();

    #pragma unroll
    for (int it = 0; it < 2; it++) {
        int idx = tid + it*256;            // 0..511: 16 rows x 32 float4
        int row = idx >> 5, c4 = idx & 31;
        float4 acc = make_float4(0.f, 0.f, 0.f, 0.f);
        for (int c = 0; c < nch; c++) {
            float4 p = *(const float4*)&g_po[(size_t)(base+c)*16384 + (r0+row)*128 + c4*4];
            float wv = ws[c][row];
            acc.x += wv*p.x; acc.y += wv*p.y; acc.z += wv*p.z; acc.w += wv*p.w;
        }
        float iv = invd[row];
        acc.x *= iv; acc.y *= iv; acc.z *= iv; acc.w *= iv;
        *(float4*)&out[((size_t)bb*T_ + qt*128 + r0 + row)*H_ + c4*4] = acc;
    }
}

// ---------------------------------------------------------------------------
extern "C" void kernel_launch(void* const* d_in, const int* in_sizes, int n_in,
                              void* d_out, int out_size)
{
    const float* x  = (const float*)d_in[0];
    const float* Wq = (const float*)d_in[1];
    const float* bq = (const float*)d_in[2];
    const float* Wk = (const float*)d_in[3];
    const float* bk = (const float*)d_in[4];
    const float* Wv = (const float*)d_in[5];
    const float* bv = (const float*)d_in[6];
    float* out = (float*)d_out;

    convert_kernel<<<96, 256>>>(Wq, Wk, Wv);

    cudaFuncSetAttribute(qkv_kernel,
                         cudaFuncAttributeMaxDynamicSharedMemorySize, QKV_SMEM_BYTES);
    qkv_kernel<<<dim3(M_/64, 3), 256, QKV_SMEM_BYTES>>>(x, bq, bk, bv);

    cudaFuncSetAttribute(attn_kernel,
                         cudaFuncAttributeMaxDynamicSharedMemorySize, ATT_SMEM_BYTES);
    attn_kernel<<<dim3(34, B_), 256, ATT_SMEM_BYTES>>>(out);

    merge_kernel<<<dim3(11, B_, 8), 256>>>(out);
}